// round 4
// baseline (speedup 1.0000x reference)
#include <cuda_runtime.h>
#include <cuda_bf16.h>
#include <cstdint>

#define HIDDEN 64
#define BT 128          // threads per render block
#define SPT 16          // depth samples per thread
#define PROWS 17        // table rows per half (suffix 0..16, prefix 17..33)

__device__ unsigned g_tab[8 * 128 * 128 * 4];   // 8 OR-dilation variants (dx,dy,dz)

// ---------------- fused pack + dilate ----------------
// 64 blocks (8x8 tiles of 16x16 (z,y) rows), 256 threads.
// Phase 1: pack 17x17 halo rows (128 voxels each) into shared bit-words.
// Phase 2: build 8 OR-dilation variants, write coalesced uint4 per row.
__global__ __launch_bounds__(256) void pack_dilate_kernel(const float* __restrict__ vol) {
    __shared__ uint4 sp[17 * 17];   // packed rows: 4 words per (z,y) row

    const int by = (blockIdx.x & 7) << 4;
    const int bz = (blockIdx.x >> 3) << 4;
    const int t = threadIdx.x;

    for (int r = t; r < 17 * 17; r += 256) {
        const int ly = r % 17, lz = r / 17;
        const int y = by + ly, z = bz + lz;
        uint4 wd = make_uint4(0u, 0u, 0u, 0u);
        if (y < 128 && z < 128) {
            const float4* src = (const float4*)(vol + (((z << 7) + y) << 7));
            unsigned ww[4];
            #pragma unroll
            for (int w = 0; w < 4; w++) {
                unsigned acc = 0;
                #pragma unroll
                for (int q = 0; q < 8; q++) {
                    float4 v = __ldg(&src[w * 8 + q]);
                    unsigned nib = (unsigned)(v.x != 0.0f)
                                 | ((unsigned)(v.y != 0.0f) << 1)
                                 | ((unsigned)(v.z != 0.0f) << 2)
                                 | ((unsigned)(v.w != 0.0f) << 3);
                    acc |= nib << (q * 4);
                }
                ww[w] = acc;
            }
            wd = make_uint4(ww[0], ww[1], ww[2], ww[3]);
        }
        sp[r] = wd;
    }
    __syncthreads();

    const int ly = t & 15, lz = t >> 4;
    const int y = by + ly, z = bz + lz;

    const unsigned* s00 = (const unsigned*)&sp[lz * 17 + ly];
    const unsigned* s01 = (const unsigned*)&sp[lz * 17 + ly + 1];
    const unsigned* s10 = (const unsigned*)&sp[(lz + 1) * 17 + ly];
    const unsigned* s11 = (const unsigned*)&sp[(lz + 1) * 17 + ly + 1];

    unsigned v0[4], v1[4], v2[4], v3[4], v4[4], v5[4], v6[4], v7[4];
    #pragma unroll
    for (int w = 0; w < 4; w++) {
        const unsigned r00 = s00[w], r01 = s01[w], r10 = s10[w], r11 = s11[w];
        const bool wp = w < 3;
        const unsigned n00 = wp ? (s00[w + 1] << 31) : 0u;
        const unsigned n01 = wp ? (s01[w + 1] << 31) : 0u;
        const unsigned n10 = wp ? (s10[w + 1] << 31) : 0u;
        const unsigned n11 = wp ? (s11[w + 1] << 31) : 0u;
        const unsigned a2 = r00 | r01, a4 = r00 | r10, a6 = a2 | a4 | r11;
        const unsigned m2 = n00 | n01, m4 = n00 | n10, m6 = m2 | m4 | n11;
        v0[w] = r00;
        v1[w] = r00 | (r00 >> 1) | n00;
        v2[w] = a2;
        v3[w] = a2 | (a2 >> 1) | m2;
        v4[w] = a4;
        v5[w] = a4 | (a4 >> 1) | m4;
        v6[w] = a6;
        v7[w] = a6 | (a6 >> 1) | m6;
    }

    uint4* dst = (uint4*)g_tab;
    const int rowi = (z << 7) + y;
    dst[0 * 16384 + rowi] = make_uint4(v0[0], v0[1], v0[2], v0[3]);
    dst[1 * 16384 + rowi] = make_uint4(v1[0], v1[1], v1[2], v1[3]);
    dst[2 * 16384 + rowi] = make_uint4(v2[0], v2[1], v2[2], v2[3]);
    dst[3 * 16384 + rowi] = make_uint4(v3[0], v3[1], v3[2], v3[3]);
    dst[4 * 16384 + rowi] = make_uint4(v4[0], v4[1], v4[2], v4[3]);
    dst[5 * 16384 + rowi] = make_uint4(v5[0], v5[1], v5[2], v5[3]);
    dst[6 * 16384 + rowi] = make_uint4(v6[0], v6[1], v6[2], v6[3]);
    dst[7 * 16384 + rowi] = make_uint4(v7[0], v7[1], v7[2], v7[3]);
}

// ---------------- render ----------------
// grid 512 x 128 threads: blockIdx&127 -> jcol, blockIdx>>7 -> i-tile (32 rows)
// lane -> i ; warp (0..3) -> 16 consecutive depth samples
__global__ __launch_bounds__(BT) void render_kernel(const float* __restrict__ T4,
                                                    const float* __restrict__ W1,
                                                    const float* __restrict__ b1,
                                                    const float* __restrict__ W2p,
                                                    const float* __restrict__ b2p,
                                                    float* __restrict__ out) {
    __shared__ float4 sE[HIDDEN];            // A, delta, w2, -1/delta
    __shared__ float4 sBC[HIDDEN];           // B, C, D, b1
    __shared__ float  sV[4 * HIDDEN];        // per (kslot,hidden): py*B+pz0*C+(D+b1)
    __shared__ float2 sTab[2 * PROWS * BT];  // suffix rows 0..16, prefix rows 17..33
    __shared__ float  red[4][32];

    const int t = threadIdx.x;
    if (t < HIDDEN) {
        float w0 = W1[t], w1 = W1[HIDDEN + t], w2 = W1[2 * HIDDEN + t];
        float A = w0 * T4[0] + w1 * T4[4] + w2 * T4[8];
        float B = w0 * T4[1] + w1 * T4[5] + w2 * T4[9];
        float C = w0 * T4[2] + w1 * T4[6] + w2 * T4[10];
        float D = w0 * T4[3] + w1 * T4[7] + w2 * T4[11];
        float dl = C * 2.0f;  // DZ
        sE[t]  = make_float4(A, dl, W2p[t], -1.0f / dl);
        sBC[t] = make_float4(B, C, D, b1[t]);
    }
    __syncthreads();

    const int lane = t & 31;
    const int kslot = t >> 5;                 // 0..3
    const int jcol = blockIdx.x & 127;
    const int i = ((blockIdx.x >> 7) << 5) + lane;
    const float px = (float)i - 63.5f;
    const float py = (float)jcol - 63.5f;

    for (int s = t; s < 4 * HIDDEN; s += BT) {
        int jh = s & 63, ks = s >> 6;
        float pz0 = ((float)(ks * SPT) - 31.5f) * 2.0f;
        float4 bc = sBC[jh];
        float Db = bc.z + bc.w;
        sV[s] = fmaf(py, bc.x, fmaf(pz0, bc.y, Db));
    }
    __syncthreads();

    const float t00 = __ldg(T4 + 0), t01 = __ldg(T4 + 1), t02 = __ldg(T4 + 2), t03 = __ldg(T4 + 3);
    const float t10 = __ldg(T4 + 4), t11 = __ldg(T4 + 5), t12 = __ldg(T4 + 6), t13 = __ldg(T4 + 7);
    const float t20 = __ldg(T4 + 8), t21 = __ldg(T4 + 9), t22 = __ldg(T4 + 10), t23 = __ldg(T4 + 11);
    const float t30 = __ldg(T4 + 12), t31 = __ldg(T4 + 13), t32 = __ldg(T4 + 14), t33 = __ldg(T4 + 15);
    const bool rigid = (t30 == 0.0f) && (t31 == 0.0f) && (t32 == 0.0f) && (t33 == 1.0f);

    const float cx = fmaf(py, t01, fmaf(px, t00, t03));
    const float cy = fmaf(py, t11, fmaf(px, t10, t13));
    const float cz = fmaf(py, t21, fmaf(px, t20, t23));
    const float cw = fmaf(py, t31, fmaf(px, t30, t33));

    const float EPS = 2e-4f;
    unsigned mb = 0;
    float dminAll = 1.0f;
    float pz = ((float)(kslot * SPT) - 31.5f) * 2.0f;

    // ---- fast mask loop (no per-iter ballot) ----
    #pragma unroll 4
    for (int m = 0; m < SPT; m++) {
        const float qx = fmaf(pz, t02, cx);
        const float qy = fmaf(pz, t12, cy);
        const float qz = fmaf(pz, t22, cz);

        const float xg = qx + 63.5f, yg = qy + 63.5f, zg = qz + 63.5f;
        const float xf = floorf(xg), yf = floorf(yg), zf = floorf(zg);
        const float fx = xg - xf, fy = yg - yf, fz = zg - zf;
        const float dmin = fminf(fminf(fminf(fx, 1.0f - fx), fminf(fy, 1.0f - fy)),
                                 fminf(fz, 1.0f - fz));
        dminAll = fminf(dminAll, dmin);

        const int x0 = (int)xf, y0 = (int)yf, z0 = (int)zf;
        // fast path: frac strictly inside (0,1) assumed; validated by dminAll below
        const bool okx = (x0 >= -1) && (x0 <= 127);
        const bool oky = (y0 >= -1) && (y0 <= 127);
        const bool okz = (z0 >= -1) && (z0 <= 127);
        unsigned bit = 0;
        if (okx && oky && okz) {
            const int dxk = (x0 >= 0) ? 1 : 0;
            const int dyk = (y0 >= 0) ? 1 : 0;
            const int dzk = (z0 >= 0) ? 1 : 0;
            const int xb = max(x0, 0), yb = max(y0, 0), zb = max(z0, 0);
            const int widx = ((dxk | (dyk << 1) | (dzk << 2)) << 16)
                           | (zb << 9) | (yb << 2) | (xb >> 5);
            bit = (__ldg(&g_tab[widx]) >> (xb & 31)) & 1u;
        }
        mb |= bit << m;
        pz += 2.0f;
    }

    // ---- rare exact recompute when any frac is near a voxel boundary ----
    if (__any_sync(0xffffffffu, dminAll < EPS)) {
        mb = 0;
        float pz2 = ((float)(kslot * SPT) - 31.5f) * 2.0f;
        for (int m = 0; m < SPT; m++) {
            const float qx = fmaf(pz2, t02, cx);
            const float qy = fmaf(pz2, t12, cy);
            const float qz = fmaf(pz2, t22, cz);
            const float xn = __fdiv_rn(qx, 63.5f), yn = __fdiv_rn(qy, 63.5f), zn = __fdiv_rn(qz, 63.5f);
            const float xg = __fmul_rn(__fmul_rn(__fadd_rn(xn, 1.0f), 0.5f), 127.0f);
            const float yg = __fmul_rn(__fmul_rn(__fadd_rn(yn, 1.0f), 0.5f), 127.0f);
            const float zg = __fmul_rn(__fmul_rn(__fadd_rn(zn, 1.0f), 0.5f), 127.0f);
            const float xf = floorf(xg), yf = floorf(yg), zf = floorf(zg);
            const int x0 = (int)xf, y0 = (int)yf, z0 = (int)zf;
            const bool bx = xg > xf, by_ = yg > yf, bz_ = zg > zf;
            const bool okx = (x0 >= -1) && (x0 <= 127) && (bx || x0 >= 0);
            const bool oky = (y0 >= -1) && (y0 <= 127) && (by_ || y0 >= 0);
            const bool okz = (z0 >= -1) && (z0 <= 127) && (bz_ || z0 >= 0);
            unsigned bit = 0;
            if (okx && oky && okz) {
                const int dxk = (bx && x0 >= 0) ? 1 : 0;
                const int dyk = (by_ && y0 >= 0) ? 1 : 0;
                const int dzk = (bz_ && z0 >= 0) ? 1 : 0;
                const int xb = max(x0, 0), yb = max(y0, 0), zb = max(z0, 0);
                const int widx = ((dxk | (dyk << 1) | (dzk << 2)) << 16)
                               | (zb << 9) | (yb << 2) | (xb >> 5);
                bit = (__ldg(&g_tab[widx]) >> (xb & 31)) & 1u;
            }
            mb |= bit << m;
            pz2 += 2.0f;
        }
    }

    // ---- per-thread suffix (rows 0..16) and prefix (rows 17..33) tables ----
    float2* tb = sTab + t;
    {
        float c0 = 0.0f, c1 = 0.0f;
        tb[16 * BT] = make_float2(0.0f, 0.0f);
        #pragma unroll
        for (int s = SPT - 1; s >= 0; --s) {
            if ((mb >> s) & 1u) { c0 += 1.0f; c1 += (float)s; }
            tb[s * BT] = make_float2(c0, c1);
        }
        float p0 = 0.0f, p1 = 0.0f;
        tb[17 * BT] = make_float2(0.0f, 0.0f);
        #pragma unroll
        for (int s = 0; s < SPT; ++s) {
            if ((mb >> s) & 1u) { p0 += 1.0f; p1 += (float)s; }
            tb[(18 + s) * BT] = make_float2(p0, p1);
        }
    }
    const float tot0 = tb[0].x;

    const float b2v = __ldg(b2p);
    float part = 0.0f;

    const unsigned act = __ballot_sync(0xffffffffu, mb != 0);
    if (act) {
        if (rigid) {
            const float* sVk = sV + kslot * HIDDEN;
            float acc0 = 0.0f, acc1 = 0.0f;
            #pragma unroll 16
            for (int jh = 0; jh < HIDDEN; jh += 2) {
                {
                    float4 e = sE[jh];
                    float u0 = fmaf(px, e.x, sVk[jh]);
                    float g = u0 * e.w;
                    int tt = __float2int_ru(g);
                    tt = min(max(tt, 0), SPT);
                    if (e.w > 0.0f) tt += PROWS;
                    float2 s = tb[tt * BT];
                    acc0 = fmaf(e.z, fmaf(e.y, s.y, u0 * s.x), acc0);
                }
                {
                    float4 e = sE[jh + 1];
                    float u0 = fmaf(px, e.x, sVk[jh + 1]);
                    float g = u0 * e.w;
                    int tt = __float2int_ru(g);
                    tt = min(max(tt, 0), SPT);
                    if (e.w > 0.0f) tt += PROWS;
                    float2 s = tb[tt * BT];
                    acc1 = fmaf(e.z, fmaf(e.y, s.y, u0 * s.x), acc1);
                }
            }
            part = fmaf(b2v, tot0, acc0 + acc1);
        } else {
            float pot = 0.0f;
            for (int m = 0; m < SPT; m++) {
                if ((mb >> m) & 1u) {
                    float pzm = ((float)(kslot * SPT + m) - 31.5f) * 2.0f;
                    float qw = fmaf(pzm, t32, cw);
                    float rcp = __fdiv_rn(1.0f, qw);
                    float s = 0.0f;
                    for (int jh = 0; jh < HIDDEN; jh++) {
                        float4 e = sE[jh];
                        float4 bc = sBC[jh];
                        float u = fmaf(px, e.x, fmaf(py, bc.x, fmaf(pzm, bc.y, bc.z)));
                        float a = fmaf(u, rcp, bc.w);
                        s = fmaf(fmaxf(a, 0.0f), e.z, s);
                    }
                    pot += s + b2v;
                }
            }
            part = pot;
        }
    }

    red[kslot][lane] = part;
    __syncthreads();
    if (kslot == 0) {
        float s = ((red[0][lane] + red[1][lane]) + red[2][lane]) + red[3][lane];
        out[i * 128 + jcol] = s * 2.0f;  // * DZ
    }
}

// ---------------- launch ----------------
extern "C" void kernel_launch(void* const* d_in, const int* in_sizes, int n_in,
                              void* d_out, int out_size) {
    const float* T  = (const float*)d_in[0];
    const float* V  = (const float*)d_in[1];
    const float* W1 = (const float*)d_in[2];
    const float* b1 = (const float*)d_in[3];
    const float* W2 = (const float*)d_in[4];
    const float* b2 = (const float*)d_in[5];
    float* out = (float*)d_out;

    pack_dilate_kernel<<<64, 256>>>(V);
    render_kernel<<<4 * 128, BT>>>(T, W1, b1, W2, b2, out);
}

// round 5
// speedup vs baseline: 1.1015x; 1.1015x over previous
#include <cuda_runtime.h>
#include <cuda_bf16.h>
#include <cstdint>

#define HIDDEN 64
#define BT 256          // threads per render block (8 warps)
#define TBL 128         // logical mask threads (4 kslots x 32 lanes)
#define SPT 16          // depth samples per logical thread
#define PROWS 17        // table rows per half (suffix 0..16, prefix 17..33)

__device__ unsigned g_tab[8 * 128 * 128 * 4];   // 8 OR-dilation variants (dx,dy,dz)

// ---------------- fused pack + dilate ----------------
__global__ __launch_bounds__(256) void pack_dilate_kernel(const float* __restrict__ vol) {
    __shared__ uint4 sp[17 * 17];

    const int by = (blockIdx.x & 7) << 4;
    const int bz = (blockIdx.x >> 3) << 4;
    const int t = threadIdx.x;

    for (int r = t; r < 17 * 17; r += 256) {
        const int ly = r % 17, lz = r / 17;
        const int y = by + ly, z = bz + lz;
        uint4 wd = make_uint4(0u, 0u, 0u, 0u);
        if (y < 128 && z < 128) {
            const float4* src = (const float4*)(vol + (((z << 7) + y) << 7));
            unsigned ww[4];
            #pragma unroll
            for (int w = 0; w < 4; w++) {
                unsigned acc = 0;
                #pragma unroll
                for (int q = 0; q < 8; q++) {
                    float4 v = __ldg(&src[w * 8 + q]);
                    unsigned nib = (unsigned)(v.x != 0.0f)
                                 | ((unsigned)(v.y != 0.0f) << 1)
                                 | ((unsigned)(v.z != 0.0f) << 2)
                                 | ((unsigned)(v.w != 0.0f) << 3);
                    acc |= nib << (q * 4);
                }
                ww[w] = acc;
            }
            wd = make_uint4(ww[0], ww[1], ww[2], ww[3]);
        }
        sp[r] = wd;
    }
    __syncthreads();

    const int ly = t & 15, lz = t >> 4;
    const int y = by + ly, z = bz + lz;

    const unsigned* s00 = (const unsigned*)&sp[lz * 17 + ly];
    const unsigned* s01 = (const unsigned*)&sp[lz * 17 + ly + 1];
    const unsigned* s10 = (const unsigned*)&sp[(lz + 1) * 17 + ly];
    const unsigned* s11 = (const unsigned*)&sp[(lz + 1) * 17 + ly + 1];

    unsigned v0[4], v1[4], v2[4], v3[4], v4[4], v5[4], v6[4], v7[4];
    #pragma unroll
    for (int w = 0; w < 4; w++) {
        const unsigned r00 = s00[w], r01 = s01[w], r10 = s10[w], r11 = s11[w];
        const bool wp = w < 3;
        const unsigned n00 = wp ? (s00[w + 1] << 31) : 0u;
        const unsigned n01 = wp ? (s01[w + 1] << 31) : 0u;
        const unsigned n10 = wp ? (s10[w + 1] << 31) : 0u;
        const unsigned n11 = wp ? (s11[w + 1] << 31) : 0u;
        const unsigned a2 = r00 | r01, a4 = r00 | r10, a6 = a2 | a4 | r11;
        const unsigned m2 = n00 | n01, m4 = n00 | n10, m6 = m2 | m4 | n11;
        v0[w] = r00;
        v1[w] = r00 | (r00 >> 1) | n00;
        v2[w] = a2;
        v3[w] = a2 | (a2 >> 1) | m2;
        v4[w] = a4;
        v5[w] = a4 | (a4 >> 1) | m4;
        v6[w] = a6;
        v7[w] = a6 | (a6 >> 1) | m6;
    }

    uint4* dst = (uint4*)g_tab;
    const int rowi = (z << 7) + y;
    dst[0 * 16384 + rowi] = make_uint4(v0[0], v0[1], v0[2], v0[3]);
    dst[1 * 16384 + rowi] = make_uint4(v1[0], v1[1], v1[2], v1[3]);
    dst[2 * 16384 + rowi] = make_uint4(v2[0], v2[1], v2[2], v2[3]);
    dst[3 * 16384 + rowi] = make_uint4(v3[0], v3[1], v3[2], v3[3]);
    dst[4 * 16384 + rowi] = make_uint4(v4[0], v4[1], v4[2], v4[3]);
    dst[5 * 16384 + rowi] = make_uint4(v5[0], v5[1], v5[2], v5[3]);
    dst[6 * 16384 + rowi] = make_uint4(v6[0], v6[1], v6[2], v6[3]);
    dst[7 * 16384 + rowi] = make_uint4(v7[0], v7[1], v7[2], v7[3]);
}

// ---------------- render ----------------
// grid 512 x 256 threads: blockIdx&127 -> jcol, blockIdx>>7 -> i-tile (32 rows)
// lane -> i ; (warp&3) -> kslot (16 depth samples) ; (warp>>2) -> hidden half
// warps 0-3: mask + tables (warps 4-7 fill sV meanwhile); all warps: 32-hidden MLP.
__global__ __launch_bounds__(BT) void render_kernel(const float* __restrict__ T4,
                                                    const float* __restrict__ W1,
                                                    const float* __restrict__ b1,
                                                    const float* __restrict__ W2p,
                                                    const float* __restrict__ b2p,
                                                    float* __restrict__ out) {
    __shared__ float4 sE[HIDDEN];            // A, delta, w2, -1/delta
    __shared__ float4 sBC[HIDDEN];           // B, C, D, b1
    __shared__ float  sV[4 * HIDDEN];        // per (kslot,hidden): py*B+pz0*C+(D+b1)
    __shared__ float2 sTab[2 * PROWS * TBL]; // suffix rows 0..16, prefix rows 17..33
    __shared__ float  red[8][32];

    const int t = threadIdx.x;
    if (t < HIDDEN) {
        float w0 = W1[t], w1 = W1[HIDDEN + t], w2 = W1[2 * HIDDEN + t];
        float A = w0 * T4[0] + w1 * T4[4] + w2 * T4[8];
        float B = w0 * T4[1] + w1 * T4[5] + w2 * T4[9];
        float C = w0 * T4[2] + w1 * T4[6] + w2 * T4[10];
        float D = w0 * T4[3] + w1 * T4[7] + w2 * T4[11];
        float dl = C * 2.0f;  // DZ
        sE[t]  = make_float4(A, dl, W2p[t], -1.0f / dl);
        sBC[t] = make_float4(B, C, D, b1[t]);
    }
    __syncthreads();

    const int lane = t & 31;
    const int w = t >> 5;
    const int kslot = w & 3;                  // 0..3
    const int jhalf = w >> 2;                 // 0..1
    const int tl = t & 127;                   // table column
    const int jcol = blockIdx.x & 127;
    const int i = ((blockIdx.x >> 7) << 5) + lane;
    const float px = (float)i - 63.5f;
    const float py = (float)jcol - 63.5f;

    const float t00 = __ldg(T4 + 0), t01 = __ldg(T4 + 1), t02 = __ldg(T4 + 2), t03 = __ldg(T4 + 3);
    const float t10 = __ldg(T4 + 4), t11 = __ldg(T4 + 5), t12 = __ldg(T4 + 6), t13 = __ldg(T4 + 7);
    const float t20 = __ldg(T4 + 8), t21 = __ldg(T4 + 9), t22 = __ldg(T4 + 10), t23 = __ldg(T4 + 11);
    const float t30 = __ldg(T4 + 12), t31 = __ldg(T4 + 13), t32 = __ldg(T4 + 14), t33 = __ldg(T4 + 15);
    const bool rigid = (t30 == 0.0f) && (t31 == 0.0f) && (t32 == 0.0f) && (t33 == 1.0f);

    const float cx = fmaf(py, t01, fmaf(px, t00, t03));
    const float cy = fmaf(py, t11, fmaf(px, t10, t13));
    const float cz = fmaf(py, t21, fmaf(px, t20, t23));
    const float cw = fmaf(py, t31, fmaf(px, t30, t33));

    unsigned mb = 0;

    if (jhalf == 1) {
        // fill sV while mask warps gather
        for (int s = tl; s < 4 * HIDDEN; s += TBL) {
            int jh = s & 63, ks = s >> 6;
            float pz0 = ((float)(ks * SPT) - 31.5f) * 2.0f;
            float4 bc = sBC[jh];
            sV[s] = fmaf(py, bc.x, fmaf(pz0, bc.y, bc.z + bc.w));
        }
    } else {
        // ---- mask loop with per-iteration near-boundary guard ----
        const float EPS = 6e-5f;
        float pz = ((float)(kslot * SPT) - 31.5f) * 2.0f;
        #pragma unroll 4
        for (int m = 0; m < SPT; m++) {
            const float qx = fmaf(pz, t02, cx);
            const float qy = fmaf(pz, t12, cy);
            const float qz = fmaf(pz, t22, cz);

            float xg = qx + 63.5f, yg = qy + 63.5f, zg = qz + 63.5f;
            float xf = floorf(xg), yf = floorf(yg), zf = floorf(zg);
            const float fx = xg - xf, fy = yg - yf, fz = zg - zf;
            const float dmin = fminf(fminf(fminf(fx, 1.0f - fx), fminf(fy, 1.0f - fy)),
                                     fminf(fz, 1.0f - fz));
            int x0, y0, z0;
            bool bx, by_, bz_;
            if (__any_sync(0xffffffffu, dmin < EPS)) {
                const float xn = __fdiv_rn(qx, 63.5f), yn = __fdiv_rn(qy, 63.5f), zn = __fdiv_rn(qz, 63.5f);
                const float xge = __fmul_rn(__fmul_rn(__fadd_rn(xn, 1.0f), 0.5f), 127.0f);
                const float yge = __fmul_rn(__fmul_rn(__fadd_rn(yn, 1.0f), 0.5f), 127.0f);
                const float zge = __fmul_rn(__fmul_rn(__fadd_rn(zn, 1.0f), 0.5f), 127.0f);
                const float xfe = floorf(xge), yfe = floorf(yge), zfe = floorf(zge);
                x0 = (int)xfe; y0 = (int)yfe; z0 = (int)zfe;
                bx = xge > xfe; by_ = yge > yfe; bz_ = zge > zfe;
            } else {
                x0 = (int)xf; y0 = (int)yf; z0 = (int)zf;
                bx = true; by_ = true; bz_ = true;
            }

            const bool okx = (x0 >= -1) && (x0 <= 127) && (bx || x0 >= 0);
            const bool oky = (y0 >= -1) && (y0 <= 127) && (by_ || y0 >= 0);
            const bool okz = (z0 >= -1) && (z0 <= 127) && (bz_ || z0 >= 0);
            unsigned bit = 0;
            if (okx && oky && okz) {
                const int dxk = (bx && x0 >= 0) ? 1 : 0;
                const int dyk = (by_ && y0 >= 0) ? 1 : 0;
                const int dzk = (bz_ && z0 >= 0) ? 1 : 0;
                const int xb = max(x0, 0), yb = max(y0, 0), zb = max(z0, 0);
                const int widx = ((dxk | (dyk << 1) | (dzk << 2)) << 16)
                               | (zb << 9) | (yb << 2) | (xb >> 5);
                bit = (__ldg(&g_tab[widx]) >> (xb & 31)) & 1u;
            }
            mb |= bit << m;
            pz += 2.0f;
        }

        // ---- per-thread suffix (rows 0..16) and prefix (rows 17..33) tables ----
        float2* tbw = sTab + tl;
        float c0 = 0.0f, c1 = 0.0f;
        tbw[16 * TBL] = make_float2(0.0f, 0.0f);
        #pragma unroll
        for (int s = SPT - 1; s >= 0; --s) {
            if ((mb >> s) & 1u) { c0 += 1.0f; c1 += (float)s; }
            tbw[s * TBL] = make_float2(c0, c1);
        }
        float p0 = 0.0f, p1 = 0.0f;
        tbw[17 * TBL] = make_float2(0.0f, 0.0f);
        #pragma unroll
        for (int s = 0; s < SPT; ++s) {
            if ((mb >> s) & 1u) { p0 += 1.0f; p1 += (float)s; }
            tbw[(18 + s) * TBL] = make_float2(p0, p1);
        }
    }
    __syncthreads();

    const float2* tb = sTab + tl;
    const float tot0 = tb[0].x;
    const float b2v = __ldg(b2p);
    float part = 0.0f;

    const unsigned act = __ballot_sync(0xffffffffu, tot0 != 0.0f);
    if (act) {
        if (rigid) {
            const float* sVk = sV + kslot * HIDDEN;
            const int jh0 = jhalf << 5;
            float acc0 = 0.0f, acc1 = 0.0f;
            #pragma unroll 8
            for (int jh = jh0; jh < jh0 + 32; jh += 2) {
                {
                    float4 e = sE[jh];
                    float u0 = fmaf(px, e.x, sVk[jh]);
                    float g = u0 * e.w;
                    int tt = __float2int_ru(g);
                    tt = min(max(tt, 0), SPT);
                    if (e.w > 0.0f) tt += PROWS;
                    float2 s = tb[tt * TBL];
                    acc0 = fmaf(e.z, fmaf(e.y, s.y, u0 * s.x), acc0);
                }
                {
                    float4 e = sE[jh + 1];
                    float u0 = fmaf(px, e.x, sVk[jh + 1]);
                    float g = u0 * e.w;
                    int tt = __float2int_ru(g);
                    tt = min(max(tt, 0), SPT);
                    if (e.w > 0.0f) tt += PROWS;
                    float2 s = tb[tt * TBL];
                    acc1 = fmaf(e.z, fmaf(e.y, s.y, u0 * s.x), acc1);
                }
            }
            part = acc0 + acc1;
            if (jhalf == 0) part = fmaf(b2v, tot0, part);
        } else if (jhalf == 0) {
            // general path (homogeneous divide): mask warps do full 64-hidden exact eval
            float pot = 0.0f;
            for (int m = 0; m < SPT; m++) {
                if ((mb >> m) & 1u) {
                    float pzm = ((float)(kslot * SPT + m) - 31.5f) * 2.0f;
                    float qw = fmaf(pzm, t32, cw);
                    float rcp = __fdiv_rn(1.0f, qw);
                    float s = 0.0f;
                    for (int jh = 0; jh < HIDDEN; jh++) {
                        float4 e = sE[jh];
                        float4 bc = sBC[jh];
                        float u = fmaf(px, e.x, fmaf(py, bc.x, fmaf(pzm, bc.y, bc.z)));
                        float a = fmaf(u, rcp, bc.w);
                        s = fmaf(fmaxf(a, 0.0f), e.z, s);
                    }
                    pot += s + b2v;
                }
            }
            part = pot;
        }
    }

    red[w][lane] = part;
    __syncthreads();
    if (t < 32) {
        float s = 0.0f;
        #pragma unroll
        for (int ww = 0; ww < 8; ww++) s += red[ww][lane];
        out[i * 128 + jcol] = s * 2.0f;  // * DZ
    }
}

// ---------------- launch ----------------
extern "C" void kernel_launch(void* const* d_in, const int* in_sizes, int n_in,
                              void* d_out, int out_size) {
    const float* T  = (const float*)d_in[0];
    const float* V  = (const float*)d_in[1];
    const float* W1 = (const float*)d_in[2];
    const float* b1 = (const float*)d_in[3];
    const float* W2 = (const float*)d_in[4];
    const float* b2 = (const float*)d_in[5];
    float* out = (float*)d_out;

    pack_dilate_kernel<<<64, 256>>>(V);
    render_kernel<<<4 * 128, BT>>>(T, W1, b1, W2, b2, out);
}

// round 6
// speedup vs baseline: 1.4831x; 1.3464x over previous
#include <cuda_runtime.h>
#include <cuda_bf16.h>
#include <cstdint>

#define HIDDEN 64
#define BT 256          // threads per render block (8 warps)
#define TBL 128         // logical mask threads (4 kslots x 32 lanes)
#define SPT 16          // depth samples per logical thread
#define PROWS 17        // table rows per half (suffix 0..16, prefix 17..33)

__device__ unsigned g_tab[8 * 128 * 128 * 4];   // 8 OR-dilation variants (dx,dy,dz)

// ---------------- fused pack + dilate v2 ----------------
// 256 blocks: 16x16 grid of 8x8 (z,y) row tiles, 9x9 halo.
// Phase 1: 324 (row,word) pack tasks, 8 float4 loads each (MLP=8, line-exact).
// Phase 2: 256 (row,word) dilate tasks -> 8 coalesced variant stores.
__global__ __launch_bounds__(256) void pack_dilate_kernel(const float* __restrict__ vol) {
    __shared__ unsigned sp[81 * 4];   // 9x9 halo rows x 4 words

    const int by = (blockIdx.x & 15) << 3;
    const int bz = (blockIdx.x >> 4) << 3;
    const int t = threadIdx.x;

    #pragma unroll 2
    for (int task = t; task < 81 * 4; task += 256) {
        const int w = task & 3, r = task >> 2;
        const int ly = r % 9, lz = r / 9;
        const int y = by + ly, z = bz + lz;
        unsigned acc = 0;
        if (y < 128 && z < 128) {
            const float4* src = (const float4*)(vol + (((z << 7) + y) << 7)) + w * 8;
            #pragma unroll
            for (int q = 0; q < 8; q++) {
                float4 v = __ldg(&src[q]);
                acc |= ((unsigned)(v.x != 0.0f)
                      | ((unsigned)(v.y != 0.0f) << 1)
                      | ((unsigned)(v.z != 0.0f) << 2)
                      | ((unsigned)(v.w != 0.0f) << 3)) << (q * 4);
            }
        }
        sp[task] = acc;
    }
    __syncthreads();

    const int w = t & 3;
    const int r = t >> 2;              // 0..63
    const int ly = r & 7, lz = r >> 3;
    const unsigned* s00 = sp + (lz * 9 + ly) * 4;
    const unsigned* s01 = sp + (lz * 9 + ly + 1) * 4;
    const unsigned* s10 = sp + ((lz + 1) * 9 + ly) * 4;
    const unsigned* s11 = sp + ((lz + 1) * 9 + ly + 1) * 4;

    const unsigned r00 = s00[w], r01 = s01[w], r10 = s10[w], r11 = s11[w];
    const bool wp = w < 3;
    const unsigned n00 = wp ? (s00[w + 1] << 31) : 0u;
    const unsigned n01 = wp ? (s01[w + 1] << 31) : 0u;
    const unsigned n10 = wp ? (s10[w + 1] << 31) : 0u;
    const unsigned n11 = wp ? (s11[w + 1] << 31) : 0u;
    const unsigned a2 = r00 | r01, a4 = r00 | r10, a6 = a2 | a4 | r11;
    const unsigned m2 = n00 | n01, m4 = n00 | n10, m6 = m2 | m4 | n11;

    const int y = by + ly, z = bz + lz;
    const int base = (((z << 7) + y) << 2) + w;
    g_tab[0 * 65536 + base] = r00;
    g_tab[1 * 65536 + base] = r00 | (r00 >> 1) | n00;
    g_tab[2 * 65536 + base] = a2;
    g_tab[3 * 65536 + base] = a2 | (a2 >> 1) | m2;
    g_tab[4 * 65536 + base] = a4;
    g_tab[5 * 65536 + base] = a4 | (a4 >> 1) | m4;
    g_tab[6 * 65536 + base] = a6;
    g_tab[7 * 65536 + base] = a6 | (a6 >> 1) | m6;
}

// ---------------- render ----------------
// grid 512 x 256 threads: blockIdx&127 -> jcol, blockIdx>>7 -> i-tile (32 rows)
// lane -> i ; (warp&3) -> kslot ; (warp>>2) -> hidden half
__global__ __launch_bounds__(BT) void render_kernel(const float* __restrict__ T4,
                                                    const float* __restrict__ W1,
                                                    const float* __restrict__ b1,
                                                    const float* __restrict__ W2p,
                                                    const float* __restrict__ b2p,
                                                    float* __restrict__ out) {
    __shared__ float4 sE[HIDDEN];            // A, delta, w2, -1/delta
    __shared__ float4 sBC[HIDDEN];           // B, C, D, b1
    __shared__ float  sV[4 * HIDDEN];        // per (kslot,hidden)
    __shared__ float2 sTab[2 * PROWS * TBL]; // suffix rows 0..16, prefix rows 17..33
    __shared__ float  red[8][32];

    const int t = threadIdx.x;
    if (t < HIDDEN) {
        float w0 = W1[t], w1 = W1[HIDDEN + t], w2 = W1[2 * HIDDEN + t];
        float A = w0 * T4[0] + w1 * T4[4] + w2 * T4[8];
        float B = w0 * T4[1] + w1 * T4[5] + w2 * T4[9];
        float C = w0 * T4[2] + w1 * T4[6] + w2 * T4[10];
        float D = w0 * T4[3] + w1 * T4[7] + w2 * T4[11];
        float dl = C * 2.0f;  // DZ
        sE[t]  = make_float4(A, dl, W2p[t], -1.0f / dl);
        sBC[t] = make_float4(B, C, D, b1[t]);
    }
    __syncthreads();

    const int lane = t & 31;
    const int w = t >> 5;
    const int kslot = w & 3;
    const int jhalf = w >> 2;
    const int tl = t & 127;
    const int jcol = blockIdx.x & 127;
    const int i = ((blockIdx.x >> 7) << 5) + lane;
    const float px = (float)i - 63.5f;
    const float py = (float)jcol - 63.5f;

    const float t00 = __ldg(T4 + 0), t01 = __ldg(T4 + 1), t02 = __ldg(T4 + 2), t03 = __ldg(T4 + 3);
    const float t10 = __ldg(T4 + 4), t11 = __ldg(T4 + 5), t12 = __ldg(T4 + 6), t13 = __ldg(T4 + 7);
    const float t20 = __ldg(T4 + 8), t21 = __ldg(T4 + 9), t22 = __ldg(T4 + 10), t23 = __ldg(T4 + 11);
    const float t30 = __ldg(T4 + 12), t31 = __ldg(T4 + 13), t32 = __ldg(T4 + 14), t33 = __ldg(T4 + 15);
    const bool rigid = (t30 == 0.0f) && (t31 == 0.0f) && (t32 == 0.0f) && (t33 == 1.0f);

    const float cx = fmaf(py, t01, fmaf(px, t00, t03));
    const float cy = fmaf(py, t11, fmaf(px, t10, t13));
    const float cz = fmaf(py, t21, fmaf(px, t20, t23));
    const float cw = fmaf(py, t31, fmaf(px, t30, t33));

    unsigned mb = 0;

    if (jhalf == 1) {
        for (int s = tl; s < 4 * HIDDEN; s += TBL) {
            int jh = s & 63, ks = s >> 6;
            float pz0 = ((float)(ks * SPT) - 31.5f) * 2.0f;
            float4 bc = sBC[jh];
            sV[s] = fmaf(py, bc.x, fmaf(pz0, bc.y, bc.z + bc.w));
        }
    } else {
        // ---- branch-free fast mask loop; suspects fixed up after ----
        const float EPS = 1e-4f;
        unsigned sus = 0;
        float pz = ((float)(kslot * SPT) - 31.5f) * 2.0f;
        #pragma unroll 8
        for (int m = 0; m < SPT; m++) {
            const float qx = fmaf(pz, t02, cx);
            const float qy = fmaf(pz, t12, cy);
            const float qz = fmaf(pz, t22, cz);

            const float xg = qx + 63.5f, yg = qy + 63.5f, zg = qz + 63.5f;
            const float xf = floorf(xg), yf = floorf(yg), zf = floorf(zg);
            const float fx = xg - xf, fy = yg - yf, fz = zg - zf;
            const float dmin = fminf(fminf(fminf(fx, 1.0f - fx), fminf(fy, 1.0f - fy)),
                                     fminf(fz, 1.0f - fz));
            if (dmin < EPS) sus |= 1u << m;

            const int x0 = (int)xf, y0 = (int)yf, z0 = (int)zf;
            const bool ok = ((unsigned)(x0 + 1) <= 128u)
                          & ((unsigned)(y0 + 1) <= 128u)
                          & ((unsigned)(z0 + 1) <= 128u);
            const int dxk = (x0 >= 0) ? 1 : 0;
            const int dyk = (y0 >= 0) ? 1 : 0;
            const int dzk = (z0 >= 0) ? 1 : 0;
            const int xb = max(x0, 0), yb = max(y0, 0), zb = max(z0, 0);
            const int widx = ((dxk | (dyk << 1) | (dzk << 2)) << 16)
                           | (zb << 9) | (yb << 2) | (xb >> 5);
            unsigned bit = 0;
            if (ok) bit = (__ldg(&g_tab[widx]) >> (xb & 31)) & 1u;
            mb |= bit << m;
            pz += 2.0f;
        }

        // ---- rare exact fixup of suspect samples only ----
        if (__any_sync(0xffffffffu, sus != 0u)) {
            while (sus) {
                const int m = __ffs(sus) - 1;
                sus &= sus - 1;
                const float pzm = ((float)(kslot * SPT + m) - 31.5f) * 2.0f;
                const float qx = fmaf(pzm, t02, cx);
                const float qy = fmaf(pzm, t12, cy);
                const float qz = fmaf(pzm, t22, cz);
                const float xn = __fdiv_rn(qx, 63.5f), yn = __fdiv_rn(qy, 63.5f), zn = __fdiv_rn(qz, 63.5f);
                const float xg = __fmul_rn(__fmul_rn(__fadd_rn(xn, 1.0f), 0.5f), 127.0f);
                const float yg = __fmul_rn(__fmul_rn(__fadd_rn(yn, 1.0f), 0.5f), 127.0f);
                const float zg = __fmul_rn(__fmul_rn(__fadd_rn(zn, 1.0f), 0.5f), 127.0f);
                const float xf = floorf(xg), yf = floorf(yg), zf = floorf(zg);
                const int x0 = (int)xf, y0 = (int)yf, z0 = (int)zf;
                const bool bx = xg > xf, by_ = yg > yf, bz_ = zg > zf;
                const bool okx = ((unsigned)(x0 + 1) <= 128u) && (bx || x0 >= 0);
                const bool oky = ((unsigned)(y0 + 1) <= 128u) && (by_ || y0 >= 0);
                const bool okz = ((unsigned)(z0 + 1) <= 128u) && (bz_ || z0 >= 0);
                unsigned bit = 0;
                if (okx && oky && okz) {
                    const int dxk = (bx && x0 >= 0) ? 1 : 0;
                    const int dyk = (by_ && y0 >= 0) ? 1 : 0;
                    const int dzk = (bz_ && z0 >= 0) ? 1 : 0;
                    const int xb = max(x0, 0), yb = max(y0, 0), zb = max(z0, 0);
                    const int widx = ((dxk | (dyk << 1) | (dzk << 2)) << 16)
                                   | (zb << 9) | (yb << 2) | (xb >> 5);
                    bit = (__ldg(&g_tab[widx]) >> (xb & 31)) & 1u;
                }
                mb = (mb & ~(1u << m)) | (bit << m);
            }
        }

        // ---- per-thread suffix/prefix tables ----
        float2* tbw = sTab + tl;
        float c0 = 0.0f, c1 = 0.0f;
        tbw[16 * TBL] = make_float2(0.0f, 0.0f);
        #pragma unroll
        for (int s = SPT - 1; s >= 0; --s) {
            if ((mb >> s) & 1u) { c0 += 1.0f; c1 += (float)s; }
            tbw[s * TBL] = make_float2(c0, c1);
        }
        float p0 = 0.0f, p1 = 0.0f;
        tbw[17 * TBL] = make_float2(0.0f, 0.0f);
        #pragma unroll
        for (int s = 0; s < SPT; ++s) {
            if ((mb >> s) & 1u) { p0 += 1.0f; p1 += (float)s; }
            tbw[(18 + s) * TBL] = make_float2(p0, p1);
        }
    }
    __syncthreads();

    const float2* tb = sTab + tl;
    const float tot0 = tb[0].x;
    const float b2v = __ldg(b2p);
    float part = 0.0f;

    const unsigned act = __ballot_sync(0xffffffffu, tot0 != 0.0f);
    if (act) {
        if (rigid) {
            const float* sVk = sV + kslot * HIDDEN;
            const int jh0 = jhalf << 5;
            float acc0 = 0.0f, acc1 = 0.0f;
            #pragma unroll 8
            for (int jh = jh0; jh < jh0 + 32; jh += 2) {
                {
                    float4 e = sE[jh];
                    float u0 = fmaf(px, e.x, sVk[jh]);
                    float g = u0 * e.w;
                    int tt = __float2int_ru(g);
                    tt = min(max(tt, 0), SPT);
                    if (e.w > 0.0f) tt += PROWS;
                    float2 s = tb[tt * TBL];
                    acc0 = fmaf(e.z, fmaf(e.y, s.y, u0 * s.x), acc0);
                }
                {
                    float4 e = sE[jh + 1];
                    float u0 = fmaf(px, e.x, sVk[jh + 1]);
                    float g = u0 * e.w;
                    int tt = __float2int_ru(g);
                    tt = min(max(tt, 0), SPT);
                    if (e.w > 0.0f) tt += PROWS;
                    float2 s = tb[tt * TBL];
                    acc1 = fmaf(e.z, fmaf(e.y, s.y, u0 * s.x), acc1);
                }
            }
            part = acc0 + acc1;
            if (jhalf == 0) part = fmaf(b2v, tot0, part);
        } else if (jhalf == 0) {
            float pot = 0.0f;
            for (int m = 0; m < SPT; m++) {
                if ((mb >> m) & 1u) {
                    float pzm = ((float)(kslot * SPT + m) - 31.5f) * 2.0f;
                    float qw = fmaf(pzm, t32, cw);
                    float rcp = __fdiv_rn(1.0f, qw);
                    float s = 0.0f;
                    for (int jh = 0; jh < HIDDEN; jh++) {
                        float4 e = sE[jh];
                        float4 bc = sBC[jh];
                        float u = fmaf(px, e.x, fmaf(py, bc.x, fmaf(pzm, bc.y, bc.z)));
                        float a = fmaf(u, rcp, bc.w);
                        s = fmaf(fmaxf(a, 0.0f), e.z, s);
                    }
                    pot += s + b2v;
                }
            }
            part = pot;
        }
    }

    red[w][lane] = part;
    __syncthreads();
    if (t < 32) {
        float s = 0.0f;
        #pragma unroll
        for (int ww = 0; ww < 8; ww++) s += red[ww][lane];
        out[i * 128 + jcol] = s * 2.0f;  // * DZ
    }
}

// ---------------- launch ----------------
extern "C" void kernel_launch(void* const* d_in, const int* in_sizes, int n_in,
                              void* d_out, int out_size) {
    const float* T  = (const float*)d_in[0];
    const float* V  = (const float*)d_in[1];
    const float* W1 = (const float*)d_in[2];
    const float* b1 = (const float*)d_in[3];
    const float* W2 = (const float*)d_in[4];
    const float* b2 = (const float*)d_in[5];
    float* out = (float*)d_out;

    pack_dilate_kernel<<<256, 256>>>(V);
    render_kernel<<<4 * 128, BT>>>(T, W1, b1, W2, b2, out);
}